// round 6
// baseline (speedup 1.0000x reference)
#include <cuda_runtime.h>
#include <cuda_bf16.h>
#include <stdint.h>

// -------------------- problem constants --------------------
#define B_Q   4096
#define P_POS 4
#define DIM   768
#define N_KEY 20480               // B_Q + B_Q*P_POS

#define BM    256
#define BN    128
#define BK    64                  // 128 bytes per row per stage
#define KTILES (DIM / BK)         // 12
#define STAGES 3
#define NT_M  (B_Q / BM)          // 16
#define NT_N  (N_KEY / BN)        // 160
#define NQT   32                  // 128-wide col tiles that are query keys
#define PW    192                 // 160 direct + 32 mirror slots (2 per bm)

// TEMPERATURE = 0.07
#define INV_T        14.285714285714286f
#define LOG2E_OVER_T 20.609929155556620f

// -------------------- scratch (__device__ globals; zero-init, no allocs) -----
__device__ __align__(256) __nv_bfloat16 g_keys[(size_t)N_KEY * DIM];
__device__ float g_part[(size_t)B_Q * PW];   // unwritten slots stay 0 forever
__device__ float g_S[B_Q];
__device__ float g_sa[B_Q * P_POS];
__device__ float g_diag[B_Q];

// -------------------- PTX helpers --------------------
__device__ __forceinline__ uint32_t smem_u32(const void* p) {
    uint32_t a;
    asm("{ .reg .u64 t; cvta.to.shared.u64 t, %1; cvt.u32.u64 %0, t; }" : "=r"(a) : "l"(p));
    return a;
}
__device__ __forceinline__ float ex2f(float y) {
    float r; asm("ex2.approx.ftz.f32 %0, %1;" : "=f"(r) : "f"(y)); return r;
}
__device__ __forceinline__ void cp_async16(uint32_t dst, const void* src) {
    asm volatile("cp.async.cg.shared.global [%0], [%1], 16;" :: "r"(dst), "l"(src) : "memory");
}
__device__ __forceinline__ void cp_commit() {
    asm volatile("cp.async.commit_group;" ::: "memory");
}
template <int N>
__device__ __forceinline__ void cp_wait() {
    asm volatile("cp.async.wait_group %0;" :: "n"(N) : "memory");
}
__device__ __forceinline__ void ldsm_x4(uint32_t* r, uint32_t addr) {
    asm volatile("ldmatrix.sync.aligned.m8n8.x4.shared.b16 {%0,%1,%2,%3}, [%4];"
                 : "=r"(r[0]), "=r"(r[1]), "=r"(r[2]), "=r"(r[3]) : "r"(addr));
}
__device__ __forceinline__ void mma16816(float* c, const uint32_t* a, const uint32_t* b) {
    asm volatile(
        "mma.sync.aligned.m16n8k16.row.col.f32.bf16.bf16.f32 "
        "{%0,%1,%2,%3}, {%4,%5,%6,%7}, {%8,%9}, {%0,%1,%2,%3};"
        : "+f"(c[0]), "+f"(c[1]), "+f"(c[2]), "+f"(c[3])
        : "r"(a[0]), "r"(a[1]), "r"(a[2]), "r"(a[3]), "r"(b[0]), "r"(b[1]));
}

// -------------------- kernel 1: L2-normalize rows -> bf16 keys ---------------
__global__ void prep_normalize(const float* __restrict__ q,
                               const float* __restrict__ docs) {
    int w = threadIdx.x >> 5, l = threadIdx.x & 31;
    int row = blockIdx.x * 8 + w;
    const float* src = (row < B_Q) ? (q + (size_t)row * DIM)
                                   : (docs + (size_t)(row - B_Q) * DIM);
    float ss = 0.f;
    #pragma unroll
    for (int j = 0; j < DIM / 32; ++j) { float v = src[j * 32 + l]; ss = fmaf(v, v, ss); }
    #pragma unroll
    for (int o = 16; o > 0; o >>= 1) ss += __shfl_xor_sync(0xffffffffu, ss, o);
    float sc = 1.0f / fmaxf(sqrtf(ss), 1e-12f);
    __nv_bfloat16* dst = g_keys + (size_t)row * DIM;
    #pragma unroll
    for (int j = 0; j < DIM / 32; ++j)
        dst[j * 32 + l] = __float2bfloat16(src[j * 32 + l] * sc);
}

// -------------------- kernel 2: positive + self dots (bf16-consistent) -------
__global__ void pos_diag_dots() {
    int i = blockIdx.x;
    int w = threadIdx.x >> 5, l = threadIdx.x & 31;
    const __nv_bfloat16* qa = g_keys + (size_t)i * DIM;
    const __nv_bfloat16* kb = (w < 4) ? (g_keys + (size_t)(B_Q + i * P_POS + w) * DIM) : qa;
    float s = 0.f;
    for (int j = l; j < DIM; j += 32)
        s = fmaf(__bfloat162float(qa[j]), __bfloat162float(kb[j]), s);
    for (int o = 16; o > 0; o >>= 1) s += __shfl_xor_sync(0xffffffffu, s, o);
    if (l == 0) { if (w < 4) g_sa[i * P_POS + w] = s; else g_diag[i] = s; }
}

// -------------------- kernel 3: pipelined mma.sync GEMM + fused exp/rowsum ---
// CTA tile 256x128, 256 threads: 8 warps as 4(M) x 2(N), warp tile 64x64.
// 3 stages x (A 32KB + B 16KB). Symmetry on the q-q region (128-granular
// blocks (i,j)): skip tile iff bn >= 2bm+2; providers (bn <= 2bm-1) emit two
// half-column-sums into mirror slots 160+2bm, 160+2bm+1.
#define ST_A(s) ((s) * 49152)
#define ST_B(s) ((s) * 49152 + 32768)
#define SM_DYN  (STAGES * 49152)

__global__ __launch_bounds__(256, 1) void gemm_exp_rowsum() {
    int bn = blockIdx.x, bm = blockIdx.y;
    if (bn < NQT && bn >= 2 * bm + 2) return;          // fully-upper q-q tile
    bool do_mirror = (bn < NQT) && (bn < 2 * bm);      // bn <= 2bm-1

    extern __shared__ char smem[];
    __shared__ float rsum[2][BM];
    __shared__ float csum[4][BN];
    uint32_t sb = smem_u32(smem);

    int t = threadIdx.x, warp = t >> 5, lane = t & 31;
    int wm = warp >> 1, wn = warp & 1;                 // 4 x 2 warps; tile 64x64
    int gr = lane >> 2, gc = lane & 3;

    const char* Abase = (const char*)g_keys + (size_t)bm * BM * DIM * 2;
    const char* Bbase = (const char*)g_keys + (size_t)bn * BN * DIM * 2;

    // load slots: A 2048 chunks -> 8/thread; B 1024 -> 4/thread
    int ar[8], ac[8];
    #pragma unroll
    for (int i = 0; i < 8; ++i) { int ch = i * 256 + t; ar[i] = ch >> 3; ac[i] = ch & 7; }

    #define ISSUE_STAGE(s, kt)                                                        \
        do {                                                                          \
            _Pragma("unroll")                                                         \
            for (int i = 0; i < 8; ++i) {                                             \
                uint32_t off = (uint32_t)(ar[i] * 128) +                              \
                               (uint32_t)((ac[i] * 16) ^ ((ar[i] & 7) << 4));         \
                cp_async16(sb + ST_A(s) + off,                                        \
                           Abase + (size_t)ar[i] * (DIM * 2) + (kt) * 128 + ac[i] * 16); \
            }                                                                         \
            _Pragma("unroll")                                                         \
            for (int i = 0; i < 4; ++i) {                                             \
                uint32_t off = (uint32_t)(ar[i] * 128) +                              \
                               (uint32_t)((ac[i] * 16) ^ ((ar[i] & 7) << 4));         \
                cp_async16(sb + ST_B(s) + off,                                        \
                           Bbase + (size_t)ar[i] * (DIM * 2) + (kt) * 128 + ac[i] * 16); \
            }                                                                         \
            cp_commit();                                                              \
        } while (0)

    ISSUE_STAGE(0, 0);
    ISSUE_STAGE(1, 1);

    float c[4][8][4];
    #pragma unroll
    for (int mt = 0; mt < 4; ++mt)
        #pragma unroll
        for (int nt = 0; nt < 8; ++nt)
            #pragma unroll
            for (int r = 0; r < 4; ++r) c[mt][nt][r] = 0.f;

    int a_mr = (lane & 15);
    int a_cb = (lane >> 4) * 16;
    int b_nr = ((lane >> 3) & 1) * 8 + (lane & 7);
    int b_cb = (lane >> 4) * 16;

    for (int kt = 0; kt < KTILES; ++kt) {
        int s = kt % STAGES;
        cp_wait<STAGES - 2>();
        __syncthreads();
        if (kt + STAGES - 1 < KTILES) ISSUE_STAGE((kt + STAGES - 1) % STAGES, kt + STAGES - 1);
        else cp_commit();

        uint32_t As = sb + ST_A(s), Bs = sb + ST_B(s);
        #pragma unroll
        for (int ks = 0; ks < 4; ++ks) {
            uint32_t a[4][4], b[8][2];
            #pragma unroll
            for (int mt = 0; mt < 4; ++mt) {
                int mr = wm * 64 + mt * 16 + a_mr;
                uint32_t cb = (uint32_t)((ks * 32 + a_cb) ^ ((mr & 7) << 4));
                ldsm_x4(a[mt], As + mr * 128 + cb);
            }
            #pragma unroll
            for (int ntp = 0; ntp < 4; ++ntp) {
                int nr = wn * 64 + ntp * 16 + b_nr;
                uint32_t cb = (uint32_t)((ks * 32 + b_cb) ^ ((nr & 7) << 4));
                uint32_t r4[4];
                ldsm_x4(r4, Bs + nr * 128 + cb);
                b[ntp * 2 + 0][0] = r4[0]; b[ntp * 2 + 0][1] = r4[2];
                b[ntp * 2 + 1][0] = r4[1]; b[ntp * 2 + 1][1] = r4[3];
            }
            #pragma unroll
            for (int mt = 0; mt < 4; ++mt)
                #pragma unroll
                for (int nt = 0; nt < 8; ++nt)
                    mma16816(c[mt][nt], a[mt], b[nt]);
        }
    }

    // ---- epilogue 1: exp + row-sums (rows unique per (wm,mt,gr)) ----
    #pragma unroll
    for (int mt = 0; mt < 4; ++mt) {
        float s0 = 0.f, s1 = 0.f;
        #pragma unroll
        for (int nt = 0; nt < 8; ++nt) {
            s0 += ex2f(c[mt][nt][0] * LOG2E_OVER_T) + ex2f(c[mt][nt][1] * LOG2E_OVER_T);
            s1 += ex2f(c[mt][nt][2] * LOG2E_OVER_T) + ex2f(c[mt][nt][3] * LOG2E_OVER_T);
        }
        s0 += __shfl_xor_sync(0xffffffffu, s0, 1);
        s0 += __shfl_xor_sync(0xffffffffu, s0, 2);
        s1 += __shfl_xor_sync(0xffffffffu, s1, 1);
        s1 += __shfl_xor_sync(0xffffffffu, s1, 2);
        if (gc == 0) {
            rsum[wn][wm * 64 + mt * 16 + gr]     = s0;
            rsum[wn][wm * 64 + mt * 16 + 8 + gr] = s1;
        }
    }

    // ---- epilogue 2 (providers only): per-64-row-band column sums ----
    if (do_mirror) {
        float cs0[8], cs1[8];
        #pragma unroll
        for (int nt = 0; nt < 8; ++nt) { cs0[nt] = 0.f; cs1[nt] = 0.f; }
        #pragma unroll
        for (int mt = 0; mt < 4; ++mt)
            #pragma unroll
            for (int nt = 0; nt < 8; ++nt) {
                cs0[nt] += ex2f(c[mt][nt][0] * LOG2E_OVER_T) + ex2f(c[mt][nt][2] * LOG2E_OVER_T);
                cs1[nt] += ex2f(c[mt][nt][1] * LOG2E_OVER_T) + ex2f(c[mt][nt][3] * LOG2E_OVER_T);
            }
        #pragma unroll
        for (int nt = 0; nt < 8; ++nt) {
            #pragma unroll
            for (int o = 4; o <= 16; o <<= 1) {
                cs0[nt] += __shfl_xor_sync(0xffffffffu, cs0[nt], o);
                cs1[nt] += __shfl_xor_sync(0xffffffffu, cs1[nt], o);
            }
        }
        if (gr == 0) {                         // lanes 0..3
            #pragma unroll
            for (int nt = 0; nt < 8; ++nt) {
                int n = wn * 64 + nt * 8 + 2 * gc;
                csum[wm][n]     = cs0[nt];
                csum[wm][n + 1] = cs1[nt];
            }
        }
    }
    __syncthreads();

    g_part[(size_t)(bm * BM + t) * PW + bn] = rsum[0][t] + rsum[1][t];
    if (do_mirror && t < BN) {
        // rows of the mirrored contribution are this tile's columns
        g_part[(size_t)(bn * BN + t) * PW + 160 + 2 * bm]     = csum[0][t] + csum[1][t];
        g_part[(size_t)(bn * BN + t) * PW + 160 + 2 * bm + 1] = csum[2][t] + csum[3][t];
    }
}

// -------------------- kernel 4: reduce partials -> S[row] --------------------
__global__ void reduce_S() {
    int row = blockIdx.x * 8 + (threadIdx.x >> 5);
    int l   = threadIdx.x & 31;
    float s = 0.f;
    #pragma unroll
    for (int j = 0; j < PW / 32; ++j) s += g_part[(size_t)row * PW + j * 32 + l];
    for (int o = 16; o > 0; o >>= 1) s += __shfl_xor_sync(0xffffffffu, s, o);
    if (l == 0) g_S[row] = s;
}

// -------------------- kernel 5: finalize loss --------------------------------
__global__ void finalize_loss(float* __restrict__ out, int out_size) {
    int t = threadIdx.x;
    float acc = 0.f;
    for (int i = t; i < B_Q; i += 512) {
        float e[4], su = 0.f, sa[4];
        #pragma unroll
        for (int n = 0; n < 4; ++n) {
            sa[n] = g_sa[i * P_POS + n];
            e[n]  = ex2f(sa[n] * LOG2E_OVER_T);
            su   += e[n];
        }
        float base = g_S[i] - ex2f(g_diag[i] * LOG2E_OVER_T) - su;
        #pragma unroll
        for (int n = 0; n < 4; ++n)
            acc += logf(base + e[n]) - sa[n] * INV_T;
    }
    __shared__ float red[512];
    red[t] = acc; __syncthreads();
    for (int s = 256; s > 0; s >>= 1) { if (t < s) red[t] += red[t + s]; __syncthreads(); }
    if (t == 0) {
        float loss = red[0] / (float)(B_Q * P_POS);
        for (int j = 0; j < out_size; ++j) out[j] = loss;
    }
}

// -------------------- launch --------------------------------------------------
extern "C" void kernel_launch(void* const* d_in, const int* in_sizes, int n_in,
                              void* d_out, int out_size) {
    (void)in_sizes; (void)n_in;
    const float* q    = (const float*)d_in[0];
    const float* docs = (const float*)d_in[1];
    float* out        = (float*)d_out;

    cudaFuncSetAttribute(gemm_exp_rowsum, cudaFuncAttributeMaxDynamicSharedMemorySize, SM_DYN);

    prep_normalize<<<N_KEY / 8, 256>>>(q, docs);
    pos_diag_dots<<<B_Q, 160>>>();
    gemm_exp_rowsum<<<dim3(NT_N, NT_M), 256, SM_DYN>>>();
    reduce_S<<<B_Q / 8, 256>>>();
    finalize_loss<<<1, 512>>>(out, out_size);
}

// round 7
// speedup vs baseline: 1.2440x; 1.2440x over previous
#include <cuda_runtime.h>
#include <cuda_bf16.h>
#include <stdint.h>

// -------------------- problem constants --------------------
#define B_Q   4096
#define P_POS 4
#define DIM   768
#define N_KEY 20480               // B_Q + B_Q*P_POS

#define BM    128
#define BN    128
#define BK    64                  // 64 elems = 128 bytes per row per stage
#define KTILES (DIM / BK)         // 12
#define STAGES 3
#define NT_M  (B_Q / BM)          // 32
#define NT_N  (N_KEY / BN)        // 160
#define NQT   32                  // column tiles that are query keys
#define PW    192                 // 160 direct + 32 mirror slots

// TEMPERATURE = 0.07
#define INV_T        14.285714285714286f
#define LOG2E_OVER_T 20.609929155556620f

// Global key layout: k-tile-major, pre-swizzled (SW128 within each 8-row 1KB block):
//   byte_off(kt, r, c16) = kt*PLANE + (r>>3)*1024 + ((r&7)*128 + c16*16) ^ ((r&7)<<4)
// so a (128-row x 1-ktile) tile is one contiguous 16KB span, already in the
// SMEM layout that ldmatrix expects.
#define PLANE ((size_t)N_KEY * 128)

// -------------------- scratch (__device__ globals; zero-init, no allocs) -----
__device__ __align__(256) unsigned char g_keys[(size_t)KTILES * PLANE];
__device__ float g_part[(size_t)B_Q * PW];   // unwritten slots stay 0 forever
__device__ float g_S[B_Q];
__device__ float g_sa[B_Q * P_POS];
__device__ float g_diag[B_Q];

// -------------------- PTX helpers --------------------
__device__ __forceinline__ uint32_t smem_u32(const void* p) {
    uint32_t a;
    asm("{ .reg .u64 t; cvta.to.shared.u64 t, %1; cvt.u32.u64 %0, t; }" : "=r"(a) : "l"(p));
    return a;
}
__device__ __forceinline__ float ex2f(float y) {
    float r; asm("ex2.approx.ftz.f32 %0, %1;" : "=f"(r) : "f"(y)); return r;
}
__device__ __forceinline__ void mbar_init(uint32_t a, uint32_t cnt) {
    asm volatile("mbarrier.init.shared.b64 [%0], %1;" :: "r"(a), "r"(cnt) : "memory");
}
__device__ __forceinline__ void mbar_expect_tx(uint32_t a, uint32_t bytes) {
    asm volatile("mbarrier.arrive.expect_tx.shared.b64 _, [%0], %1;" :: "r"(a), "r"(bytes) : "memory");
}
__device__ __forceinline__ void mbar_arrive(uint32_t a) {
    asm volatile("mbarrier.arrive.shared.b64 _, [%0];" :: "r"(a) : "memory");
}
__device__ __forceinline__ void mbar_wait(uint32_t a, uint32_t ph) {
    asm volatile(
        "{\n\t.reg .pred P;\n\t"
        "LAB_%=:\n\t"
        "mbarrier.try_wait.parity.acquire.cta.shared::cta.b64 P, [%0], %1, 0x989680;\n\t"
        "@!P bra LAB_%=;\n\t}"
        :: "r"(a), "r"(ph) : "memory");
}
__device__ __forceinline__ void bulk_g2s(uint32_t dst, const void* src, uint32_t bytes,
                                         uint32_t mbar) {
    asm volatile(
        "cp.async.bulk.shared::cta.global.mbarrier::complete_tx::bytes [%0], [%1], %2, [%3];"
        :: "r"(dst), "l"(src), "r"(bytes), "r"(mbar) : "memory");
}
__device__ __forceinline__ void ldsm_x4(uint32_t* r, uint32_t addr) {
    asm volatile("ldmatrix.sync.aligned.m8n8.x4.shared.b16 {%0,%1,%2,%3}, [%4];"
                 : "=r"(r[0]), "=r"(r[1]), "=r"(r[2]), "=r"(r[3]) : "r"(addr));
}
__device__ __forceinline__ void mma16816(float* c, const uint32_t* a, const uint32_t* b) {
    asm volatile(
        "mma.sync.aligned.m16n8k16.row.col.f32.bf16.bf16.f32 "
        "{%0,%1,%2,%3}, {%4,%5,%6,%7}, {%8,%9}, {%0,%1,%2,%3};"
        : "+f"(c[0]), "+f"(c[1]), "+f"(c[2]), "+f"(c[3])
        : "r"(a[0]), "r"(a[1]), "r"(a[2]), "r"(a[3]), "r"(b[0]), "r"(b[1]));
}

// chunk index ch in [0,96): 16B chunk of a row (ktile = ch>>3, c16 = ch&7)
__device__ __forceinline__ size_t key_off(int r, int ch) {
    int kt = ch >> 3, c16 = ch & 7, rr = r & 7;
    return (size_t)kt * PLANE + (size_t)(r >> 3) * 1024
         + (uint32_t)(((rr * 128 + c16 * 16)) ^ (rr << 4));
}

// -------------------- kernel 1: L2-normalize rows -> swizzled bf16 keys ------
__global__ void prep_normalize(const float* __restrict__ q,
                               const float* __restrict__ docs) {
    int w = threadIdx.x >> 5, l = threadIdx.x & 31;
    int row = blockIdx.x * 8 + w;
    const float* src = (row < B_Q) ? (q + (size_t)row * DIM)
                                   : (docs + (size_t)(row - B_Q) * DIM);
    float ss = 0.f;
    #pragma unroll
    for (int j = 0; j < DIM / 32; ++j) { float v = src[j * 32 + l]; ss = fmaf(v, v, ss); }
    #pragma unroll
    for (int o = 16; o > 0; o >>= 1) ss += __shfl_xor_sync(0xffffffffu, ss, o);
    float sc = 1.0f / fmaxf(sqrtf(ss), 1e-12f);
    #pragma unroll
    for (int c3 = 0; c3 < 3; ++c3) {
        int ch = c3 * 32 + l;
        const float* s8 = src + ch * 8;
        uint4 u;
        uint32_t* pu = (uint32_t*)&u;
        #pragma unroll
        for (int i = 0; i < 4; ++i) {
            __nv_bfloat162 h = __floats2bfloat162_rn(s8[2 * i] * sc, s8[2 * i + 1] * sc);
            pu[i] = *(uint32_t*)&h;
        }
        *(uint4*)(g_keys + key_off(row, ch)) = u;
    }
}

// -------------------- kernel 2: positive + self dots (bf16-consistent) -------
__device__ __forceinline__ float dot8(uint4 a, uint4 b, float s) {
    const uint32_t* pa = (const uint32_t*)&a;
    const uint32_t* pb = (const uint32_t*)&b;
    #pragma unroll
    for (int i = 0; i < 4; ++i) {
        __nv_bfloat162 ha = *(const __nv_bfloat162*)&pa[i];
        __nv_bfloat162 hb = *(const __nv_bfloat162*)&pb[i];
        s = fmaf(__bfloat162float(ha.x), __bfloat162float(hb.x), s);
        s = fmaf(__bfloat162float(ha.y), __bfloat162float(hb.y), s);
    }
    return s;
}

__global__ void pos_diag_dots() {
    int i = blockIdx.x;
    int w = threadIdx.x >> 5, l = threadIdx.x & 31;
    int kr = (w < 4) ? (B_Q + i * P_POS + w) : i;
    float s = 0.f;
    #pragma unroll
    for (int c3 = 0; c3 < 3; ++c3) {
        int ch = c3 * 32 + l;
        uint4 ua = *(const uint4*)(g_keys + key_off(i, ch));
        uint4 ub = *(const uint4*)(g_keys + key_off(kr, ch));
        s = dot8(ua, ub, s);
    }
    for (int o = 16; o > 0; o >>= 1) s += __shfl_xor_sync(0xffffffffu, s, o);
    if (l == 0) { if (w < 4) g_sa[i * P_POS + w] = s; else g_diag[i] = s; }
}

// -------------------- kernel 3: bulk-TMA pipelined GEMM + fused exp/rowsum ---
// 128x128 tiles, 256 threads (2M x 4N warps; warp tile 64x32), 3 stages.
// Loads: thread 0 issues one 16KB cp.async.bulk per operand per stage.
#define ST_A(s) (128 + (s) * 32768)
#define ST_B(s) (128 + (s) * 32768 + 16384)
#define SM_DYN  (128 + STAGES * 32768)

__global__ __launch_bounds__(256, 2) void gemm_exp_rowsum() {
    int bn = blockIdx.x, bm = blockIdx.y;
    if (bn < NQT && bn > bm) return;           // upper-triangle q-q tile: mirrored
    bool do_mirror = (bn < NQT) && (bn < bm);

    extern __shared__ char smem[];
    __shared__ float rsum[4][128];
    __shared__ float csum[2][128];
    uint32_t sb = smem_u32(smem);
    uint32_t mb_full  = sb;                    // 3 x 8B
    uint32_t mb_empty = sb + 24;               // 3 x 8B

    int t = threadIdx.x, warp = t >> 5, lane = t & 31;
    int wm = warp >> 2, wn = warp & 3;          // warp tile 64(M) x 32(N)
    int gr = lane >> 2, gc = lane & 3;

    if (t == 0) {
        #pragma unroll
        for (int s = 0; s < STAGES; ++s) {
            mbar_init(mb_full + s * 8, 1);
            mbar_init(mb_empty + s * 8, 8);
        }
    }
    __syncthreads();

    const unsigned char* keys = g_keys;
    size_t aoff = (size_t)bm * 16384;
    size_t boff = (size_t)bn * 16384;

    if (t == 0) {
        #pragma unroll
        for (int k = 0; k < STAGES; ++k) {
            uint32_t f = mb_full + k * 8;
            mbar_expect_tx(f, 32768);
            bulk_g2s(sb + ST_A(k), keys + (size_t)k * PLANE + aoff, 16384, f);
            bulk_g2s(sb + ST_B(k), keys + (size_t)k * PLANE + boff, 16384, f);
        }
    }

    float c[4][4][4];
    #pragma unroll
    for (int mt = 0; mt < 4; ++mt)
        #pragma unroll
        for (int nt = 0; nt < 4; ++nt)
            #pragma unroll
            for (int r = 0; r < 4; ++r) c[mt][nt][r] = 0.f;

    int a_mr = (lane & 15);
    int a_cb = (lane >> 4) * 16;
    int b_nr = ((lane >> 3) & 1) * 8 + (lane & 7);
    int b_cb = (lane >> 4) * 16;

    for (int kt = 0; kt < KTILES; ++kt) {
        int s = kt % STAGES;
        uint32_t ph = (uint32_t)((kt / STAGES) & 1);
        mbar_wait(mb_full + s * 8, ph);

        uint32_t As = sb + ST_A(s), Bs = sb + ST_B(s);
        #pragma unroll
        for (int ks = 0; ks < 4; ++ks) {
            uint32_t a[4][4], b[4][2];
            #pragma unroll
            for (int mt = 0; mt < 4; ++mt) {
                int mr = wm * 64 + mt * 16 + a_mr;
                uint32_t cb = (uint32_t)((ks * 32 + a_cb) ^ ((mr & 7) << 4));
                ldsm_x4(a[mt], As + mr * 128 + cb);
            }
            #pragma unroll
            for (int nt2 = 0; nt2 < 2; ++nt2) {
                int nr = wn * 32 + nt2 * 16 + b_nr;
                uint32_t cb = (uint32_t)((ks * 32 + b_cb) ^ ((nr & 7) << 4));
                uint32_t r4[4];
                ldsm_x4(r4, Bs + nr * 128 + cb);
                b[nt2 * 2 + 0][0] = r4[0]; b[nt2 * 2 + 0][1] = r4[2];
                b[nt2 * 2 + 1][0] = r4[1]; b[nt2 * 2 + 1][1] = r4[3];
            }
            #pragma unroll
            for (int mt = 0; mt < 4; ++mt)
                #pragma unroll
                for (int nt = 0; nt < 4; ++nt)
                    mma16816(c[mt][nt], a[mt], b[nt]);
        }

        __syncwarp();
        if (lane == 0) mbar_arrive(mb_empty + s * 8);
        if (t == 0 && kt + STAGES < KTILES) {
            mbar_wait(mb_empty + s * 8, ph);   // all 8 warps done with stage s
            int ktn = kt + STAGES;
            uint32_t f = mb_full + s * 8;
            mbar_expect_tx(f, 32768);
            bulk_g2s(sb + ST_A(s), keys + (size_t)ktn * PLANE + aoff, 16384, f);
            bulk_g2s(sb + ST_B(s), keys + (size_t)ktn * PLANE + boff, 16384, f);
        }
    }

    // ---- epilogue: exp once; row-sums always, col-sums when mirroring ----
    float cs0[4] = {0.f, 0.f, 0.f, 0.f};
    float cs1[4] = {0.f, 0.f, 0.f, 0.f};
    #pragma unroll
    for (int mt = 0; mt < 4; ++mt) {
        float s0 = 0.f, s1 = 0.f;
        #pragma unroll
        for (int nt = 0; nt < 4; ++nt) {
            float e0 = ex2f(c[mt][nt][0] * LOG2E_OVER_T);
            float e1 = ex2f(c[mt][nt][1] * LOG2E_OVER_T);
            float e2 = ex2f(c[mt][nt][2] * LOG2E_OVER_T);
            float e3 = ex2f(c[mt][nt][3] * LOG2E_OVER_T);
            s0 += e0 + e1;  s1 += e2 + e3;
            cs0[nt] += e0 + e2;  cs1[nt] += e1 + e3;
        }
        s0 += __shfl_xor_sync(0xffffffffu, s0, 1);
        s0 += __shfl_xor_sync(0xffffffffu, s0, 2);
        s1 += __shfl_xor_sync(0xffffffffu, s1, 1);
        s1 += __shfl_xor_sync(0xffffffffu, s1, 2);
        if (gc == 0) {
            rsum[wn][wm * 64 + mt * 16 + gr]     = s0;
            rsum[wn][wm * 64 + mt * 16 + 8 + gr] = s1;
        }
    }
    if (do_mirror) {
        #pragma unroll
        for (int nt = 0; nt < 4; ++nt) {
            #pragma unroll
            for (int o = 4; o <= 16; o <<= 1) {
                cs0[nt] += __shfl_xor_sync(0xffffffffu, cs0[nt], o);
                cs1[nt] += __shfl_xor_sync(0xffffffffu, cs1[nt], o);
            }
        }
        if (gr == 0) {
            #pragma unroll
            for (int nt = 0; nt < 4; ++nt) {
                int n = wn * 32 + nt * 8 + 2 * gc;
                if (wm == 0) { csum[0][n] = cs0[nt]; csum[0][n + 1] = cs1[nt]; }
                else         { csum[1][n] = cs0[nt]; csum[1][n + 1] = cs1[nt]; }
            }
        }
    }
    __syncthreads();
    if (t < 128) {
        g_part[(size_t)(bm * BM + t) * PW + bn] =
            rsum[0][t] + rsum[1][t] + rsum[2][t] + rsum[3][t];
        if (do_mirror)
            g_part[(size_t)(bn * BN + t) * PW + 160 + bm] = csum[0][t] + csum[1][t];
    }
}

// -------------------- kernel 4: reduce partials -> S[row] --------------------
__global__ void reduce_S() {
    int row = blockIdx.x * 8 + (threadIdx.x >> 5);
    int l   = threadIdx.x & 31;
    float s = 0.f;
    #pragma unroll
    for (int j = 0; j < PW / 32; ++j) s += g_part[(size_t)row * PW + j * 32 + l];
    for (int o = 16; o > 0; o >>= 1) s += __shfl_xor_sync(0xffffffffu, s, o);
    if (l == 0) g_S[row] = s;
}

// -------------------- kernel 5: finalize loss --------------------------------
__global__ void finalize_loss(float* __restrict__ out, int out_size) {
    int t = threadIdx.x;
    float acc = 0.f;
    for (int i = t; i < B_Q; i += 512) {
        float e[4], su = 0.f, sa[4];
        #pragma unroll
        for (int n = 0; n < 4; ++n) {
            sa[n] = g_sa[i * P_POS + n];
            e[n]  = ex2f(sa[n] * LOG2E_OVER_T);
            su   += e[n];
        }
        float base = g_S[i] - ex2f(g_diag[i] * LOG2E_OVER_T) - su;
        #pragma unroll
        for (int n = 0; n < 4; ++n)
            acc += logf(base + e[n]) - sa[n] * INV_T;
    }
    __shared__ float red[512];
    red[t] = acc; __syncthreads();
    for (int s = 256; s > 0; s >>= 1) { if (t < s) red[t] += red[t + s]; __syncthreads(); }
    if (t == 0) {
        float loss = red[0] / (float)(B_Q * P_POS);
        for (int j = 0; j < out_size; ++j) out[j] = loss;
    }
}

// -------------------- launch --------------------------------------------------
extern "C" void kernel_launch(void* const* d_in, const int* in_sizes, int n_in,
                              void* d_out, int out_size) {
    (void)in_sizes; (void)n_in;
    const float* q    = (const float*)d_in[0];
    const float* docs = (const float*)d_in[1];
    float* out        = (float*)d_out;

    cudaFuncSetAttribute(gemm_exp_rowsum, cudaFuncAttributeMaxDynamicSharedMemorySize, SM_DYN);

    prep_normalize<<<N_KEY / 8, 256>>>(q, docs);
    pos_diag_dots<<<B_Q, 160>>>();
    gemm_exp_rowsum<<<dim3(NT_N, NT_M), 256, SM_DYN>>>();
    reduce_S<<<B_Q / 8, 256>>>();
    finalize_loss<<<1, 512>>>(out, out_size);
}